// round 6
// baseline (speedup 1.0000x reference)
#include <cuda_runtime.h>
#include <cuda_bf16.h>
#include <cstdint>

#define NB 4
#define NC 128
#define NH 256
#define NW 512
#define ND 64
#define W_TILE 64
#define C_TILE 64
#define THREADS 256

// SMEM (bytes): bf16 tiles, rows of 128 k-elements = 256B (16 chunks of 16B).
// Chunk-XOR swizzle: chunk' = chunk ^ (row & 7) -> ldmatrix conflict-free.
#define SM_AHI  0                       // A_hi [64m x 128k] bf16 (16KB)
#define SM_ALO  (SM_AHI + 16384)        // A_lo (16KB)
#define SM_BHI  (SM_ALO + 16384)        // B_hi [64n x 128k] bf16 (16KB)
#define SM_BLO  (SM_BHI + 16384)        // B_lo (16KB)
#define SMEM_TOTAL (SM_BLO + 16384)     // 65536 -> 3 CTAs/SM

__device__ __forceinline__ uint32_t smem_u32(const void* p) {
    uint32_t a;
    asm("{ .reg .u64 t; cvta.to.shared.u64 t, %1; cvt.u32.u64 %0, t; }" : "=r"(a) : "l"(p));
    return a;
}
__device__ __forceinline__ uint32_t tile_off(int row, int k) {
    return (uint32_t)(row * 256 + (((k >> 3) ^ (row & 7)) << 4) + (k & 7) * 2);
}
__device__ __forceinline__ void bsplit(float x, uint16_t& hi, uint16_t& lo) {
    __nv_bfloat16 h = __float2bfloat16(x);
    __nv_bfloat16 l = __float2bfloat16(x - __bfloat162float(h));
    hi = *reinterpret_cast<uint16_t*>(&h);
    lo = *reinterpret_cast<uint16_t*>(&l);
}
__device__ __forceinline__ void ldsm4(uint32_t* r, uint32_t addr) {
    asm volatile("ldmatrix.sync.aligned.m8n8.x4.shared.b16 {%0,%1,%2,%3}, [%4];"
                 : "=r"(r[0]), "=r"(r[1]), "=r"(r[2]), "=r"(r[3]) : "r"(addr));
}
__device__ __forceinline__ void mma16816(float* c, const uint32_t* a, const uint32_t* b) {
    asm volatile("mma.sync.aligned.m16n8k16.row.col.f32.bf16.bf16.f32 "
                 "{%0,%1,%2,%3}, {%4,%5,%6,%7}, {%8,%9}, {%0,%1,%2,%3};"
                 : "+f"(c[0]), "+f"(c[1]), "+f"(c[2]), "+f"(c[3])
                 : "r"(a[0]), "r"(a[1]), "r"(a[2]), "r"(a[3]), "r"(b[0]), "r"(b[1]));
}

// Band-pruned mainloop, specialized on the warp's n offset (0 or 32).
// B[w][k] nonzero iff k-w in [0,64). For n8 tile at nb: nonzero k in [nb, nb+70].
template <int NWARP>
__device__ __forceinline__ void mainloop(uint32_t smb, int m_warp,
                                         int a_m, int a_ks, int b_n, int b_ks,
                                         float acc[4][4])
{
    #pragma unroll
    for (int ks = 0; ks < 8; ks++) {
        const bool needA = (ks >= NWARP / 16) && (ks <= NWARP / 16 + 5);
        if (!needA) continue;
        uint32_t ahi[4], alo[4], bhi[2][4], blo[2][4];
        {
            const int m = m_warp + a_m;
            const uint32_t off = (uint32_t)(m * 256 + (((ks * 2 + a_ks) ^ (m & 7)) << 4));
            ldsm4(ahi, smb + SM_AHI + off);
            ldsm4(alo, smb + SM_ALO + off);
        }
        #pragma unroll
        for (int p = 0; p < 2; p++) {
            const bool needB = (ks >= NWARP / 16 + p) && (ks <= NWARP / 16 + p + 4);
            if (!needB) continue;
            const int n = NWARP + p * 16 + b_n;
            const uint32_t off = (uint32_t)(n * 256 + (((ks * 2 + b_ks) ^ (n & 7)) << 4));
            ldsm4(bhi[p], smb + SM_BHI + off);
            ldsm4(blo[p], smb + SM_BLO + off);
        }
        #pragma unroll
        for (int nt = 0; nt < 4; nt++) {
            const int nb = NWARP + nt * 8;
            const bool use = (16 * ks <= nb + 70) && (16 * ks + 15 >= nb);
            if (!use) continue;
            const uint32_t* bh = &bhi[nt >> 1][(nt & 1) * 2];
            const uint32_t* bl = &blo[nt >> 1][(nt & 1) * 2];
            mma16816(acc[nt], ahi, bh);
            mma16816(acc[nt], ahi, bl);
            mma16816(acc[nt], alo, bh);
        }
    }
}

__global__ void __launch_bounds__(THREADS, 3)
corr_mma_kernel(const float* __restrict__ h1,
                const float* __restrict__ cost,
                float* __restrict__ out)
{
    extern __shared__ char smem[];
    const uint32_t smb = smem_u32(smem);
    const int tid  = threadIdx.x;
    const int wid  = tid >> 5;
    const int lane = tid & 31;

    const int wt = blockIdx.x & 7;        // w-tile 0..7
    const int cs = blockIdx.x >> 3;       // channel slice 0..1
    const int hh = blockIdx.y;            // 0..255
    const int bb = blockIdx.z;            // 0..3
    const int w0 = wt * W_TILE;
    const int c0 = cs * C_TILE;

    // ---- Phase 1: zero B (32KB), load+split A (64 rows), fetch cost to regs ----
    {
        uint4 z = make_uint4(0, 0, 0, 0);
        #pragma unroll
        for (int j = 0; j < 8; j++)
            *reinterpret_cast<uint4*>(smem + SM_BHI + (j * THREADS + tid) * 16) = z;
    }
    {
        #pragma unroll
        for (int j = 0; j < 8; j++) {
            const int idx = j * THREADS + tid;
            const int row = idx >> 5;          // 0..63 (channel within slice)
            const int q   = idx & 31;          // float4 within row
            const int gw  = w0 + q * 4;
            float4 v = make_float4(0.f, 0.f, 0.f, 0.f);
            if (gw < NW)
                v = *reinterpret_cast<const float4*>(
                        h1 + (((size_t)bb * NC + c0 + row) * NH + hh) * NW + gw);
            uint16_t ha, la, hb2, lb, hc, lc, hd, ld;
            bsplit(v.x, ha, la); bsplit(v.y, hb2, lb);
            bsplit(v.z, hc, lc); bsplit(v.w, hd, ld);
            uint2 hp, lp;
            hp.x = (uint32_t)ha | ((uint32_t)hb2 << 16);
            hp.y = (uint32_t)hc | ((uint32_t)hd << 16);
            lp.x = (uint32_t)la | ((uint32_t)lb << 16);
            lp.y = (uint32_t)lc | ((uint32_t)ld << 16);
            const uint32_t off = tile_off(row, q * 4);
            *reinterpret_cast<uint2*>(smem + SM_AHI + off) = hp;
            *reinterpret_cast<uint2*>(smem + SM_ALO + off) = lp;
        }
    }
    float4 cv[4];
    int cd[4], cw[4];
    {
        #pragma unroll
        for (int j = 0; j < 4; j++) {
            const int idx = j * THREADS + tid;
            cd[j] = idx >> 4;          // d
            cw[j] = (idx & 15) * 4;    // w base
            cv[j] = *reinterpret_cast<const float4*>(
                        cost + (((size_t)bb * ND + cd[j]) * NH + hh) * NW + w0 + cw[j]);
        }
    }
    __syncthreads();

    // ---- Phase 2: shear-scatter cost into B: B[w][w+d] = cost[d][w] ----
    {
        #pragma unroll
        for (int j = 0; j < 4; j++) {
            const float x[4] = {cv[j].x, cv[j].y, cv[j].z, cv[j].w};
            #pragma unroll
            for (int e = 0; e < 4; e++) {
                const int w = cw[j] + e;
                const uint32_t off = tile_off(w, w + cd[j]);
                uint16_t hi, lo;
                bsplit(x[e], hi, lo);
                *reinterpret_cast<uint16_t*>(smem + SM_BHI + off) = hi;
                *reinterpret_cast<uint16_t*>(smem + SM_BLO + off) = lo;
            }
        }
    }
    __syncthreads();

    // ---- Phase 3: warp-tile GEMM. Warp = 16m x 32n; 8 warps cover 64x64 ----
    const int m_warp = (wid & 3) * 16;
    const int n_warp = (wid >> 2) * 32;
    const int qd = lane >> 2;
    const int tq = lane & 3;

    const int sub  = lane >> 3;
    const int rid  = lane & 7;
    const int a_m  = (sub & 1) * 8 + rid;
    const int a_ks = (sub >> 1);
    const int b_n  = (sub >> 1) * 8 + rid;
    const int b_ks = (sub & 1);

    float acc[4][4];
    #pragma unroll
    for (int nt = 0; nt < 4; nt++)
        #pragma unroll
        for (int e = 0; e < 4; e++) acc[nt][e] = 0.f;

    if (n_warp == 0)
        mainloop<0>(smb, m_warp, a_m, a_ks, b_n, b_ks, acc);
    else
        mainloop<32>(smb, m_warp, a_m, a_ks, b_n, b_ks, acc);

    // ---- Epilogue ----
    {
        const int m0 = c0 + m_warp + qd;
        float* r0 = out + (((size_t)bb * NC + m0) * NH + hh) * NW + w0 + n_warp;
        float* r1 = out + (((size_t)bb * NC + m0 + 8) * NH + hh) * NW + w0 + n_warp;
        #pragma unroll
        for (int nt = 0; nt < 4; nt++) {
            const int nc2 = nt * 8 + tq * 2;
            *reinterpret_cast<float2*>(r0 + nc2) = make_float2(acc[nt][0], acc[nt][1]);
            *reinterpret_cast<float2*>(r1 + nc2) = make_float2(acc[nt][2], acc[nt][3]);
        }
    }
}

extern "C" void kernel_launch(void* const* d_in, const int* in_sizes, int n_in,
                              void* d_out, int out_size)
{
    const float* h1   = (const float*)d_in[0];
    const float* cost = (const float*)d_in[1];
    float* out        = (float*)d_out;

    cudaFuncSetAttribute(corr_mma_kernel, cudaFuncAttributeMaxDynamicSharedMemorySize, SMEM_TOTAL);

    dim3 grid((NW / W_TILE) * (NC / C_TILE), NH, NB);
    corr_mma_kernel<<<grid, THREADS, SMEM_TOTAL>>>(h1, cost, out);
}